// round 1
// baseline (speedup 1.0000x reference)
#include <cuda_runtime.h>
#include <math.h>
#include <stdint.h>

// Problem shape (fixed by the reference)
#define BB 4
#define TT 4096
#define HH 1024
#define SS 64
#define MM (BB * TT)   // 16384 rows of (b,t)
#define NC 64          // scan chunks
#define LC 64          // chunk length, NC*LC == TT

// ---------------------------------------------------------------------------
// Scratch (device globals; no dynamic allocation allowed)
// ---------------------------------------------------------------------------
__device__ float g_wcat[128 * HH];              // [WB;Wg] packed, 512 KB
__device__ float g_raw[(size_t)MM * 128];       // raw Bx | gate logits, 8 MB
__device__ float g_u[(size_t)MM * SS];          // driving term, 4 MB
__device__ float g_states[(size_t)MM * SS];     // scan states, 4 MB
__device__ float g_hn[(size_t)MM * HH];         // LN output, 64 MB
__device__ float g_z[BB * NC * SS];             // chunk-local scan results
__device__ float g_carry[BB * NC * SS];         // incoming state per chunk

// ---------------------------------------------------------------------------
// Generic NT SGEMM: C[m,n] = sum_k A[m,k]*B[n,k]  (+ epilogue)
//   EPI 0: plain store
//   EPI 1: += (e0[n] + 1) * e1[m*HH + n]   (C-proj + D*x + residual)
//   EPI 2: += e0[n]                         (out-proj bias)
// ---------------------------------------------------------------------------
template <int BM, int BN, int EPI>
__global__ void __launch_bounds__((BM / 8) * (BN / 8)) gemm_nt(
    const float* __restrict__ A, const float* __restrict__ Bw,
    float* __restrict__ C, int K, int lda, int ldb, int ldc,
    const float* __restrict__ e0, const float* __restrict__ e1)
{
    constexpr int BK = 16;
    constexpr int TM = 8, TN = 8;
    constexpr int THREADS = (BM / TM) * (BN / TN);
    constexpr int A4 = BM * BK / (4 * THREADS);  // float4 loads per thread (A)
    constexpr int B4 = BN * BK / (4 * THREADS);  // float4 loads per thread (B)

    __shared__ float As[BK][BM];
    __shared__ float Bs[BK][BN];

    const int tid = threadIdx.x;
    const int row0 = blockIdx.y * BM;
    const int col0 = blockIdx.x * BN;
    const int tx = tid % (BN / TN);
    const int ty = tid / (BN / TN);

    float acc[TM][TN] = {};

    for (int k0 = 0; k0 < K; k0 += BK) {
#pragma unroll
        for (int p = 0; p < A4; p++) {
            int idx = tid + p * THREADS;
            int r = idx >> 2;
            int c = (idx & 3) << 2;
            float4 v = *reinterpret_cast<const float4*>(
                A + (size_t)(row0 + r) * lda + k0 + c);
            As[c + 0][r] = v.x; As[c + 1][r] = v.y;
            As[c + 2][r] = v.z; As[c + 3][r] = v.w;
        }
#pragma unroll
        for (int p = 0; p < B4; p++) {
            int idx = tid + p * THREADS;
            int r = idx >> 2;
            int c = (idx & 3) << 2;
            float4 v = *reinterpret_cast<const float4*>(
                Bw + (size_t)(col0 + r) * ldb + k0 + c);
            Bs[c + 0][r] = v.x; Bs[c + 1][r] = v.y;
            Bs[c + 2][r] = v.z; Bs[c + 3][r] = v.w;
        }
        __syncthreads();
#pragma unroll
        for (int k = 0; k < BK; k++) {
            float4 a0 = *reinterpret_cast<const float4*>(&As[k][ty * TM]);
            float4 a1 = *reinterpret_cast<const float4*>(&As[k][ty * TM + 4]);
            float4 b0 = *reinterpret_cast<const float4*>(&Bs[k][tx * TN]);
            float4 b1 = *reinterpret_cast<const float4*>(&Bs[k][tx * TN + 4]);
            float a[8] = {a0.x, a0.y, a0.z, a0.w, a1.x, a1.y, a1.z, a1.w};
            float b[8] = {b0.x, b0.y, b0.z, b0.w, b1.x, b1.y, b1.z, b1.w};
#pragma unroll
            for (int i = 0; i < TM; i++)
#pragma unroll
                for (int j = 0; j < TN; j++)
                    acc[i][j] = fmaf(a[i], b[j], acc[i][j]);
        }
        __syncthreads();
    }

#pragma unroll
    for (int i = 0; i < TM; i++) {
        size_t r = (size_t)row0 + ty * TM + i;
#pragma unroll
        for (int j = 0; j < TN; j++) {
            int c = col0 + tx * TN + j;
            float v = acc[i][j];
            if (EPI == 1) v += (e0[c] + 1.0f) * e1[r * HH + c];
            if (EPI == 2) v += e0[c];
            C[r * ldc + c] = v;
        }
    }
}

// ---------------------------------------------------------------------------
// Pack [WB ; Wg] into one 128 x 1024 weight matrix
// ---------------------------------------------------------------------------
__global__ void pack_w_kernel(const float* __restrict__ WB,
                              const float* __restrict__ Wg)
{
    int i = blockIdx.x * 256 + threadIdx.x;
    if (i < SS * HH) {
        g_wcat[i] = WB[i];
        g_wcat[SS * HH + i] = Wg[i];
    }
}

// u = sigmoid(gate_logit + bg) * Bx
__global__ void compute_u_kernel(const float* __restrict__ bg)
{
    int idx = blockIdx.x * blockDim.x + threadIdx.x;   // over MM*SS
    int s = idx & (SS - 1);
    int m = idx >> 6;
    float bx = g_raw[(size_t)m * 128 + s];
    float gl = g_raw[(size_t)m * 128 + 64 + s] + bg[s];
    float gate = 1.0f / (1.0f + expf(-gl));
    g_u[idx] = gate * bx;
}

// ---------------------------------------------------------------------------
// Chunked linear scan: state_t = A*state_{t-1} + u_t
// ---------------------------------------------------------------------------
__global__ void chunk_z_kernel(const float* __restrict__ A_log)
{
    int bc = blockIdx.x;                 // b*NC + c
    int b = bc / NC, c = bc % NC;
    int s = threadIdx.x;
    float a = expf(A_log[s]);
    const float* up = g_u + ((size_t)b * TT + (size_t)c * LC) * SS + s;
    float z = 0.0f;
#pragma unroll 8
    for (int i = 0; i < LC; i++) z = fmaf(a, z, up[(size_t)i * SS]);
    g_z[bc * SS + s] = z;
}

__global__ void carry_kernel(const float* __restrict__ A_log,
                             float* __restrict__ d_final, int write_final)
{
    int t = threadIdx.x;                 // 256 = BB*SS
    int b = t / SS, s = t % SS;
    float a = expf(A_log[s]);
    float aL = a;
#pragma unroll
    for (int i = 0; i < 6; i++) aL *= aL;   // a^64
    float carry = 0.0f;
    for (int c = 0; c < NC; c++) {
        g_carry[(b * NC + c) * SS + s] = carry;
        carry = fmaf(aL, carry, g_z[(b * NC + c) * SS + s]);
    }
    if (write_final) d_final[b * SS + s] = carry;   // final_state output
}

__global__ void chunk_states_kernel(const float* __restrict__ A_log)
{
    int bc = blockIdx.x;
    int b = bc / NC, c = bc % NC;
    int s = threadIdx.x;
    float a = expf(A_log[s]);
    float st = g_carry[bc * SS + s];
    size_t base = ((size_t)b * TT + (size_t)c * LC) * SS + s;
#pragma unroll 8
    for (int i = 0; i < LC; i++) {
        st = fmaf(a, st, g_u[base + (size_t)i * SS]);
        g_states[base + (size_t)i * SS] = st;
    }
}

// ---------------------------------------------------------------------------
// Row LayerNorm over g_hn (in place), 1 block per (b,t) row
// ---------------------------------------------------------------------------
__global__ void __launch_bounds__(256) ln_kernel(const float* __restrict__ gamma,
                                                 const float* __restrict__ beta)
{
    __shared__ float red[16];
    size_t row = blockIdx.x;
    float4* h4 = reinterpret_cast<float4*>(g_hn + row * HH);
    int t = threadIdx.x;
    float4 v = h4[t];
    float sum = v.x + v.y + v.z + v.w;
    float sq = v.x * v.x + v.y * v.y + v.z * v.z + v.w * v.w;
#pragma unroll
    for (int o = 16; o > 0; o >>= 1) {
        sum += __shfl_xor_sync(0xffffffffu, sum, o);
        sq  += __shfl_xor_sync(0xffffffffu, sq, o);
    }
    if ((t & 31) == 0) { red[t >> 5] = sum; red[8 + (t >> 5)] = sq; }
    __syncthreads();
    sum = 0.0f; sq = 0.0f;
#pragma unroll
    for (int i = 0; i < 8; i++) { sum += red[i]; sq += red[8 + i]; }
    float mu = sum * (1.0f / HH);
    float var = sq * (1.0f / HH) - mu * mu;
    float inv = rsqrtf(var + 1e-5f);
    float4 g4 = reinterpret_cast<const float4*>(gamma)[t];
    float4 b4 = reinterpret_cast<const float4*>(beta)[t];
    v.x = (v.x - mu) * inv * g4.x + b4.x;
    v.y = (v.y - mu) * inv * g4.y + b4.y;
    v.z = (v.z - mu) * inv * g4.z + b4.z;
    v.w = (v.w - mu) * inv * g4.w + b4.w;
    h4[t] = v;
}

// ---------------------------------------------------------------------------
// Launcher (graph-capturable: kernel launches only, default stream)
// ---------------------------------------------------------------------------
extern "C" void kernel_launch(void* const* d_in, const int* in_sizes, int n_in,
                              void* d_out, int out_size)
{
    const float* x     = (const float*)d_in[0];
    const float* A_log = (const float*)d_in[1];
    const float* WB    = (const float*)d_in[2];
    const float* WC    = (const float*)d_in[3];
    const float* D     = (const float*)d_in[4];
    const float* Wg    = (const float*)d_in[5];
    const float* bg    = (const float*)d_in[6];
    const float* Wout  = (const float*)d_in[7];
    const float* bout  = (const float*)d_in[8];
    const float* gamma = (const float*)d_in[9];
    const float* beta  = (const float*)d_in[10];
    float* out = (float*)d_out;

    // Resolve scratch symbol addresses (no allocation; capture-safe queries)
    float *p_wcat, *p_raw, *p_states, *p_hn;
    cudaGetSymbolAddress((void**)&p_wcat,   g_wcat);
    cudaGetSymbolAddress((void**)&p_raw,    g_raw);
    cudaGetSymbolAddress((void**)&p_states, g_states);
    cudaGetSymbolAddress((void**)&p_hn,     g_hn);

    // 1) pack weights, project x -> [Bx | gate logits]
    pack_w_kernel<<<(SS * HH + 255) / 256, 256>>>(WB, Wg);
    gemm_nt<64, 128, 0><<<dim3(1, MM / 64), 128>>>(
        x, p_wcat, p_raw, HH, HH, HH, 128, nullptr, nullptr);
    compute_u_kernel<<<(MM * SS) / 256, 256>>>(bg);

    // 2) chunked diagonal scan
    chunk_z_kernel<<<BB * NC, SS>>>(A_log);
    int write_final = (out_size >= MM * HH + BB * SS) ? 1 : 0;
    carry_kernel<<<1, BB * SS>>>(A_log, out + (size_t)MM * HH, write_final);
    chunk_states_kernel<<<BB * NC, SS>>>(A_log);

    // 3) C-projection + D*x + residual -> h ; LayerNorm in place
    gemm_nt<128, 128, 1><<<dim3(HH / 128, MM / 128), 256>>>(
        p_states, WC, p_hn, SS, SS, SS, HH, D, x);
    ln_kernel<<<MM, 256>>>(gamma, beta);

    // 4) out-projection + bias (dominant GEMM)
    gemm_nt<128, 128, 2><<<dim3(HH / 128, MM / 128), 256>>>(
        p_hn, Wout, out, HH, HH, HH, HH, bout, nullptr);
}

// round 3
// speedup vs baseline: 2.9563x; 2.9563x over previous
#include <cuda_runtime.h>
#include <math.h>
#include <stdint.h>

// Problem shape (fixed by the reference)
#define BB 4
#define TT 4096
#define HH 1024
#define SS 64
#define MM (BB * TT)   // 16384 rows of (b,t)
#define NC 64          // scan chunks
#define LC 64          // chunk length, NC*LC == TT

// ---------------------------------------------------------------------------
// Scratch (device globals; no dynamic allocation allowed)
// ---------------------------------------------------------------------------
__device__ float g_wcat[128 * HH];              // [WB;Wg] packed, 512 KB
__device__ float g_raw[(size_t)MM * 128];       // raw Bx | gate logits, 8 MB
__device__ float g_u[(size_t)MM * SS];          // driving term, 4 MB
__device__ float g_states[(size_t)MM * SS];     // scan states, 4 MB
__device__ float g_hn[(size_t)MM * HH];         // LN output, 64 MB
__device__ float g_z[BB * NC * SS];             // chunk-local scan results
__device__ float g_carry[BB * NC * SS];         // incoming state per chunk

// ---------------------------------------------------------------------------
// tf32 helpers
// ---------------------------------------------------------------------------
__device__ __forceinline__ unsigned f2tf32(float f) {
    unsigned u;
    asm("cvt.rna.tf32.f32 %0, %1;" : "=r"(u) : "f"(f));
    return u;
}

__device__ __forceinline__ void mma_tf32(float& d0, float& d1, float& d2, float& d3,
                                         unsigned a0, unsigned a1, unsigned a2, unsigned a3,
                                         unsigned b0, unsigned b1) {
    asm volatile(
        "mma.sync.aligned.m16n8k8.row.col.f32.tf32.tf32.f32 "
        "{%0,%1,%2,%3}, {%4,%5,%6,%7}, {%8,%9}, {%0,%1,%2,%3};"
        : "+f"(d0), "+f"(d1), "+f"(d2), "+f"(d3)
        : "r"(a0), "r"(a1), "r"(a2), "r"(a3), "r"(b0), "r"(b1));
}

// ---------------------------------------------------------------------------
// tf32 tensor-core NT GEMM: C[m,n] = sum_k A[m,k]*B[n,k]  (+ epilogue)
//   EPI 0: plain store
//   EPI 1: += (e0[n] + 1) * e1[m*HH + n]   (C-proj + D*x + residual)
//   EPI 2: += e0[n]                         (out-proj bias)
// BM=BN=128, BK=32, 256 threads (8 warps; each computes a 64x32 microtile).
// ---------------------------------------------------------------------------
template <int EPI>
__global__ void __launch_bounds__(256) gemm_tf32(
    const float* __restrict__ A, const float* __restrict__ Bw,
    float* __restrict__ C, int K, int lda, int ldb, int ldc,
    const float* __restrict__ e0, const float* __restrict__ e1)
{
    constexpr int BM = 128, BK = 32;
    constexpr int PAD = 36;                 // stride 36 => conflict-free frag LDS

    __shared__ unsigned As[BM * PAD];
    __shared__ unsigned Bs[BM * PAD];

    const int tid = threadIdx.x;
    const int lane = tid & 31;
    const int warp = tid >> 5;
    const int wM = warp >> 2;               // 0..1  (64-row slabs)
    const int wN = warp & 3;                // 0..3  (32-col slabs)
    const int gID = lane >> 2;              // 0..7
    const int tig = lane & 3;               // 0..3

    const int row0 = blockIdx.y * BM;
    const int col0 = blockIdx.x * BM;

    float acc[4][4][4];                     // [mt][nt][frag]
#pragma unroll
    for (int i = 0; i < 4; i++)
#pragma unroll
        for (int j = 0; j < 4; j++)
#pragma unroll
            for (int f = 0; f < 4; f++) acc[i][j][f] = 0.0f;

    float4 ra[4], rb[4];

    auto gload = [&](int k0) {
#pragma unroll
        for (int p = 0; p < 4; p++) {
            int idx = tid + p * 256;        // 0..1023
            int r = idx >> 3;               // 0..127
            int c = (idx & 7) << 2;         // 0,4,...,28
            ra[p] = *reinterpret_cast<const float4*>(A + (size_t)(row0 + r) * lda + k0 + c);
            rb[p] = *reinterpret_cast<const float4*>(Bw + (size_t)(col0 + r) * ldb + k0 + c);
        }
    };
    auto sstore = [&]() {
#pragma unroll
        for (int p = 0; p < 4; p++) {
            int idx = tid + p * 256;
            int r = idx >> 3;
            int c = (idx & 7) << 2;
            unsigned* ap = &As[r * PAD + c];
            ap[0] = f2tf32(ra[p].x); ap[1] = f2tf32(ra[p].y);
            ap[2] = f2tf32(ra[p].z); ap[3] = f2tf32(ra[p].w);
            unsigned* bp = &Bs[r * PAD + c];
            bp[0] = f2tf32(rb[p].x); bp[1] = f2tf32(rb[p].y);
            bp[2] = f2tf32(rb[p].z); bp[3] = f2tf32(rb[p].w);
        }
    };

    gload(0);
    for (int k0 = 0; k0 < K; k0 += BK) {
        sstore();
        __syncthreads();
        if (k0 + BK < K) gload(k0 + BK);    // next tile's GMEM loads overlap compute

#pragma unroll
        for (int ks = 0; ks < BK / 8; ks++) {
            const int kk = ks * 8;
            unsigned af[4][4], bf[4][2];
#pragma unroll
            for (int mt = 0; mt < 4; mt++) {
                int r = wM * 64 + mt * 16 + gID;
                af[mt][0] = As[r * PAD + kk + tig];
                af[mt][1] = As[(r + 8) * PAD + kk + tig];
                af[mt][2] = As[r * PAD + kk + tig + 4];
                af[mt][3] = As[(r + 8) * PAD + kk + tig + 4];
            }
#pragma unroll
            for (int nt = 0; nt < 4; nt++) {
                int c = wN * 32 + nt * 8 + gID;
                bf[nt][0] = Bs[c * PAD + kk + tig];
                bf[nt][1] = Bs[c * PAD + kk + tig + 4];
            }
#pragma unroll
            for (int mt = 0; mt < 4; mt++)
#pragma unroll
                for (int nt = 0; nt < 4; nt++)
                    mma_tf32(acc[mt][nt][0], acc[mt][nt][1], acc[mt][nt][2], acc[mt][nt][3],
                             af[mt][0], af[mt][1], af[mt][2], af[mt][3],
                             bf[nt][0], bf[nt][1]);
        }
        __syncthreads();
    }

    // epilogue: c0,c1 -> (row, col..col+1); c2,c3 -> (row+8, ...)
#pragma unroll
    for (int mt = 0; mt < 4; mt++) {
        size_t r = (size_t)row0 + wM * 64 + mt * 16 + gID;
#pragma unroll
        for (int nt = 0; nt < 4; nt++) {
            int c = col0 + wN * 32 + nt * 8 + 2 * tig;
            float v0 = acc[mt][nt][0], v1 = acc[mt][nt][1];
            float v2 = acc[mt][nt][2], v3 = acc[mt][nt][3];
            if (EPI == 1) {
                float d0 = e0[c] + 1.0f, d1 = e0[c + 1] + 1.0f;
                v0 += d0 * e1[r * HH + c];       v1 += d1 * e1[r * HH + c + 1];
                v2 += d0 * e1[(r + 8) * HH + c]; v3 += d1 * e1[(r + 8) * HH + c + 1];
            }
            if (EPI == 2) {
                v0 += e0[c]; v1 += e0[c + 1];
                v2 += e0[c]; v3 += e0[c + 1];
            }
            *reinterpret_cast<float2*>(C + r * ldc + c) = make_float2(v0, v1);
            *reinterpret_cast<float2*>(C + (r + 8) * ldc + c) = make_float2(v2, v3);
        }
    }
}

// ---------------------------------------------------------------------------
// Pack [WB ; Wg] into one 128 x 1024 weight matrix
// ---------------------------------------------------------------------------
__global__ void pack_w_kernel(const float* __restrict__ WB,
                              const float* __restrict__ Wg)
{
    int i = blockIdx.x * 256 + threadIdx.x;
    if (i < SS * HH) {
        g_wcat[i] = WB[i];
        g_wcat[SS * HH + i] = Wg[i];
    }
}

// u = sigmoid(gate_logit + bg) * Bx
__global__ void compute_u_kernel(const float* __restrict__ bg)
{
    int idx = blockIdx.x * blockDim.x + threadIdx.x;   // over MM*SS
    int s = idx & (SS - 1);
    int m = idx >> 6;
    float bx = g_raw[(size_t)m * 128 + s];
    float gl = g_raw[(size_t)m * 128 + 64 + s] + bg[s];
    float gate = 1.0f / (1.0f + expf(-gl));
    g_u[idx] = gate * bx;
}

// ---------------------------------------------------------------------------
// Chunked linear scan: state_t = A*state_{t-1} + u_t
// ---------------------------------------------------------------------------
__global__ void chunk_z_kernel(const float* __restrict__ A_log)
{
    int bc = blockIdx.x;                 // b*NC + c
    int b = bc / NC, c = bc % NC;
    int s = threadIdx.x;
    float a = expf(A_log[s]);
    const float* up = g_u + ((size_t)b * TT + (size_t)c * LC) * SS + s;
    float z = 0.0f;
#pragma unroll 8
    for (int i = 0; i < LC; i++) z = fmaf(a, z, up[(size_t)i * SS]);
    g_z[bc * SS + s] = z;
}

__global__ void carry_kernel(const float* __restrict__ A_log,
                             float* __restrict__ d_final, int write_final)
{
    int t = threadIdx.x;                 // 256 = BB*SS
    int b = t / SS, s = t % SS;
    float a = expf(A_log[s]);
    float aL = a;
#pragma unroll
    for (int i = 0; i < 6; i++) aL *= aL;   // a^64
    float carry = 0.0f;
    for (int c = 0; c < NC; c++) {
        g_carry[(b * NC + c) * SS + s] = carry;
        carry = fmaf(aL, carry, g_z[(b * NC + c) * SS + s]);
    }
    if (write_final) d_final[b * SS + s] = carry;   // final_state output
}

__global__ void chunk_states_kernel(const float* __restrict__ A_log)
{
    int bc = blockIdx.x;
    int b = bc / NC, c = bc % NC;
    int s = threadIdx.x;
    float a = expf(A_log[s]);
    float st = g_carry[bc * SS + s];
    size_t base = ((size_t)b * TT + (size_t)c * LC) * SS + s;
#pragma unroll 8
    for (int i = 0; i < LC; i++) {
        st = fmaf(a, st, g_u[base + (size_t)i * SS]);
        g_states[base + (size_t)i * SS] = st;
    }
}

// ---------------------------------------------------------------------------
// Row LayerNorm over g_hn (in place), 1 block per (b,t) row
// ---------------------------------------------------------------------------
__global__ void __launch_bounds__(256) ln_kernel(const float* __restrict__ gamma,
                                                 const float* __restrict__ beta)
{
    __shared__ float red[16];
    size_t row = blockIdx.x;
    float4* h4 = reinterpret_cast<float4*>(g_hn + row * HH);
    int t = threadIdx.x;
    float4 v = h4[t];
    float sum = v.x + v.y + v.z + v.w;
    float sq = v.x * v.x + v.y * v.y + v.z * v.z + v.w * v.w;
#pragma unroll
    for (int o = 16; o > 0; o >>= 1) {
        sum += __shfl_xor_sync(0xffffffffu, sum, o);
        sq  += __shfl_xor_sync(0xffffffffu, sq, o);
    }
    if ((t & 31) == 0) { red[t >> 5] = sum; red[8 + (t >> 5)] = sq; }
    __syncthreads();
    sum = 0.0f; sq = 0.0f;
#pragma unroll
    for (int i = 0; i < 8; i++) { sum += red[i]; sq += red[8 + i]; }
    float mu = sum * (1.0f / HH);
    float var = sq * (1.0f / HH) - mu * mu;
    float inv = rsqrtf(var + 1e-5f);
    float4 g4 = reinterpret_cast<const float4*>(gamma)[t];
    float4 b4 = reinterpret_cast<const float4*>(beta)[t];
    v.x = (v.x - mu) * inv * g4.x + b4.x;
    v.y = (v.y - mu) * inv * g4.y + b4.y;
    v.z = (v.z - mu) * inv * g4.z + b4.z;
    v.w = (v.w - mu) * inv * g4.w + b4.w;
    h4[t] = v;
}

// ---------------------------------------------------------------------------
// Launcher (graph-capturable: kernel launches only, default stream)
// ---------------------------------------------------------------------------
extern "C" void kernel_launch(void* const* d_in, const int* in_sizes, int n_in,
                              void* d_out, int out_size)
{
    const float* x     = (const float*)d_in[0];
    const float* A_log = (const float*)d_in[1];
    const float* WB    = (const float*)d_in[2];
    const float* WC    = (const float*)d_in[3];
    const float* D     = (const float*)d_in[4];
    const float* Wg    = (const float*)d_in[5];
    const float* bg    = (const float*)d_in[6];
    const float* Wout  = (const float*)d_in[7];
    const float* bout  = (const float*)d_in[8];
    const float* gamma = (const float*)d_in[9];
    const float* beta  = (const float*)d_in[10];
    float* out = (float*)d_out;

    // Resolve scratch symbol addresses (no allocation; capture-safe queries)
    float *p_wcat, *p_raw, *p_states, *p_hn;
    cudaGetSymbolAddress((void**)&p_wcat,   g_wcat);
    cudaGetSymbolAddress((void**)&p_raw,    g_raw);
    cudaGetSymbolAddress((void**)&p_states, g_states);
    cudaGetSymbolAddress((void**)&p_hn,     g_hn);

    // 1) pack weights, project x -> [Bx | gate logits]
    pack_w_kernel<<<(SS * HH + 255) / 256, 256>>>(WB, Wg);
    gemm_tf32<0><<<dim3(1, MM / 128), 256>>>(
        x, p_wcat, p_raw, HH, HH, HH, 128, nullptr, nullptr);
    compute_u_kernel<<<(MM * SS) / 256, 256>>>(bg);

    // 2) chunked diagonal scan
    chunk_z_kernel<<<BB * NC, SS>>>(A_log);
    int write_final = (out_size >= MM * HH + BB * SS) ? 1 : 0;
    carry_kernel<<<1, BB * SS>>>(A_log, out + (size_t)MM * HH, write_final);
    chunk_states_kernel<<<BB * NC, SS>>>(A_log);

    // 3) C-projection + D*x + residual -> h ; LayerNorm in place
    gemm_tf32<1><<<dim3(HH / 128, MM / 128), 256>>>(
        p_states, WC, p_hn, SS, SS, SS, HH, D, x);
    ln_kernel<<<MM, 256>>>(gamma, beta);

    // 4) out-projection + bias (dominant GEMM)
    gemm_tf32<2><<<dim3(HH / 128, MM / 128), 256>>>(
        p_hn, Wout, out, HH, HH, HH, HH, bout, nullptr);
}